// round 3
// baseline (speedup 1.0000x reference)
#include <cuda_runtime.h>

#define BB 4096
#define TT 16
#define HH 768
#define AA 128
#define VV 16
#define LL 2
#define MTILE 32
#define KC 128
#define NC 128
#define XPAD 36
#define NTHREADS 256
#define MAXTILES 160

// ---- device-global scratch ----
__device__ int g_counts[VV];
__device__ int g_bins[VV * BB];
__device__ int g_ntiles;
__device__ int g_tiles[MAXTILES];

__global__ void va_zero_counts() {
    if (threadIdx.x < VV) g_counts[threadIdx.x] = 0;
}

__global__ void va_bin(const int* __restrict__ vids) {
    int b = blockIdx.x * blockDim.x + threadIdx.x;
    if (b < BB) {
        int v = vids[b];
        int slot = atomicAdd(&g_counts[v], 1);
        g_bins[v * BB + slot] = b;
    }
}

__global__ void va_build_tiles() {
    if (threadIdx.x == 0) {
        int t = 0;
        for (int v = 0; v < VV; v++) {
            int c = g_counts[v];
            for (int r0 = 0; r0 < c; r0 += MTILE)
                g_tiles[t++] = (v << 16) | (r0 / MTILE);
        }
        g_ntiles = t;
    }
}

// ---- f32x2 packed-FMA helpers ----
typedef unsigned long long u64t;

__device__ __forceinline__ u64t dup2(float x) {
    u64t r;
    asm("mov.b64 %0, {%1, %1};" : "=l"(r) : "f"(x));
    return r;
}
__device__ __forceinline__ u64t fma2(u64t a, u64t b, u64t c) {
    u64t d;
    asm("fma.rn.f32x2 %0, %1, %2, %3;" : "=l"(d) : "l"(a), "l"(b), "l"(c));
    return d;
}
__device__ __forceinline__ float2 upk(u64t d) {
    float2 f;
    asm("mov.b64 {%0, %1}, %2;" : "=f"(f.x), "=f"(f.y) : "l"(d));
    return f;
}

__device__ __forceinline__ float gelu_tanh(float x) {
    float x3 = x * x * x;
    float t = tanhf(0.7978845608028654f * (x + 0.044715f * x3));
    return 0.5f * x * (1.0f + t);
}

// smem: sXt[HH][XPAD] + sHt[AA][XPAD] + sW[128*128]
#define SMEM_FLOATS (HH * XPAD + AA * XPAD + 128 * 128)

extern "C" __global__ void __launch_bounds__(NTHREADS, 1)
va_main(const float* __restrict__ lh,
        const float* __restrict__ Wd, const float* __restrict__ bd,
        const float* __restrict__ Wu, const float* __restrict__ bu,
        const float* __restrict__ Wc, const float* __restrict__ bc,
        float* __restrict__ out) {
    extern __shared__ float smem[];
    float* sXt = smem;
    float* sHt = smem + HH * XPAD;
    float* sW  = smem + HH * XPAD + AA * XPAD;
    __shared__ int sB[MTILE];

    const int tid  = threadIdx.x;
    const int lane = tid & 31;
    const int warp = tid >> 5;
    const int rg   = lane & 15;          // row group: rows 2*rg, 2*rg+1
    const int ch   = lane >> 4;          // col half within warp
    const int cg8  = (2 * warp + ch) * 8;  // thread's 8 output cols (mod 128)

    const int ntiles = g_ntiles;

    for (int t = blockIdx.x; t < ntiles; t += gridDim.x) {
        const int info = g_tiles[t];
        const int v    = info >> 16;
        const int row0 = (info & 0xFFFF) * MTILE;
        const int cnt  = g_counts[v];

        if (tid < MTILE) {
            int gr = row0 + tid;
            sB[tid] = (gr < cnt) ? g_bins[v * BB + gr] : -1;
        }
        __syncthreads();

        // ---- weight prefetch for GEMM1 stage 0 (overlaps gather) ----
        const float* Wdv = Wd + (size_t)v * HH * AA;
        float4 pf[16];
        #pragma unroll
        for (int q = 0; q < 16; q++)
            pf[q] = *(const float4*)(Wdv + (size_t)(q * NTHREADS + tid) * 4);

        // ---- gather 32 x rows (t=0) transposed into sXt ----
        for (int idx = tid; idx < MTILE * (HH / 4); idx += NTHREADS) {
            int r  = idx / (HH / 4);
            int k4 = idx % (HH / 4);
            int b  = sB[r];
            float4 val = make_float4(0.f, 0.f, 0.f, 0.f);
            if (b >= 0)
                val = *(const float4*)(lh + (size_t)b * TT * HH + k4 * 4);
            sXt[(k4 * 4 + 0) * XPAD + r] = val.x;
            sXt[(k4 * 4 + 1) * XPAD + r] = val.y;
            sXt[(k4 * 4 + 2) * XPAD + r] = val.z;
            sXt[(k4 * 4 + 3) * XPAD + r] = val.w;
        }

        u64t acc1[2][4];
        #pragma unroll
        for (int i = 0; i < 2; i++)
            #pragma unroll
            for (int j = 0; j < 4; j++) acc1[i][j] = 0ull;

        __syncthreads();   // sXt ready; sW free (prev tile done)

        // ================ GEMM1: H[32][128] = X[32][768] @ Wd[v] ================
        for (int k0 = 0; k0 < HH; k0 += KC) {
            #pragma unroll
            for (int q = 0; q < 16; q++)
                *(float4*)(sW + (q * NTHREADS + tid) * 4) = pf[q];
            __syncthreads();
            if (k0 + KC < HH) {
                const float* src = Wdv + (size_t)(k0 + KC) * AA;
                #pragma unroll
                for (int q = 0; q < 16; q++)
                    pf[q] = *(const float4*)(src + (size_t)(q * NTHREADS + tid) * 4);
            }
            #pragma unroll 4
            for (int kk = 0; kk < KC; kk++) {
                float2 a2 = *(const float2*)(sXt + (k0 + kk) * XPAD + 2 * rg);
                double2 B0 = *(const double2*)(sW + kk * AA + cg8);
                double2 B1 = *(const double2*)(sW + kk * AA + cg8 + 4);
                u64t a0 = dup2(a2.x), a1 = dup2(a2.y);
                u64t b0 = __double_as_longlong(B0.x);
                u64t b1 = __double_as_longlong(B0.y);
                u64t b2 = __double_as_longlong(B1.x);
                u64t b3 = __double_as_longlong(B1.y);
                acc1[0][0] = fma2(a0, b0, acc1[0][0]);
                acc1[0][1] = fma2(a0, b1, acc1[0][1]);
                acc1[0][2] = fma2(a0, b2, acc1[0][2]);
                acc1[0][3] = fma2(a0, b3, acc1[0][3]);
                acc1[1][0] = fma2(a1, b0, acc1[1][0]);
                acc1[1][1] = fma2(a1, b1, acc1[1][1]);
                acc1[1][2] = fma2(a1, b2, acc1[1][2]);
                acc1[1][3] = fma2(a1, b3, acc1[1][3]);
            }
            __syncthreads();
        }

        // ---- GEMM2 stage-0 prefetch (overlaps gelu) ----
        const float* Wuv = Wu + (size_t)v * AA * HH;
        #pragma unroll
        for (int q = 0; q < 16; q++) {
            int idx4 = q * NTHREADS + tid;
            int a    = idx4 >> 5;
            int cc4  = idx4 & 31;
            pf[q] = *(const float4*)(Wuv + (size_t)a * HH + cc4 * 4);
        }

        // ---- bias + gelu -> sHt transposed ----
        {
            const float* bdv = bd + v * AA;
            float hv[2][8];
            #pragma unroll
            for (int i = 0; i < 2; i++)
                #pragma unroll
                for (int j2 = 0; j2 < 4; j2++) {
                    float2 f = upk(acc1[i][j2]);
                    hv[i][2 * j2 + 0] = gelu_tanh(f.x + bdv[cg8 + 2 * j2 + 0]);
                    hv[i][2 * j2 + 1] = gelu_tanh(f.y + bdv[cg8 + 2 * j2 + 1]);
                }
            #pragma unroll
            for (int j = 0; j < 8; j++)
                *(float2*)(sHt + (cg8 + j) * XPAD + 2 * rg) =
                    make_float2(hv[0][j], hv[1][j]);
        }
        __syncthreads();

        // ======= GEMM2 (6 col tiles of 128) + residual + classifier =======
        const float* buv = bu + v * HH;
        float outacc[2][2];
        outacc[0][0] = outacc[0][1] = outacc[1][0] = outacc[1][1] = 0.f;

        for (int c0 = 0; c0 < HH; c0 += NC) {
            #pragma unroll
            for (int q = 0; q < 16; q++) {
                int idx4 = q * NTHREADS + tid;
                int a    = idx4 >> 5;
                int cc4  = idx4 & 31;
                *(float4*)(sW + a * NC + cc4 * 4) = pf[q];
            }
            __syncthreads();
            if (c0 + NC < HH) {
                #pragma unroll
                for (int q = 0; q < 16; q++) {
                    int idx4 = q * NTHREADS + tid;
                    int a    = idx4 >> 5;
                    int cc4  = idx4 & 31;
                    pf[q] = *(const float4*)(Wuv + (size_t)a * HH + (c0 + NC) + cc4 * 4);
                }
            }

            u64t acc2[2][4];
            #pragma unroll
            for (int i = 0; i < 2; i++)
                #pragma unroll
                for (int j = 0; j < 4; j++) acc2[i][j] = 0ull;

            #pragma unroll 4
            for (int kk = 0; kk < AA; kk++) {
                float2 a2 = *(const float2*)(sHt + kk * XPAD + 2 * rg);
                double2 B0 = *(const double2*)(sW + kk * NC + cg8);
                double2 B1 = *(const double2*)(sW + kk * NC + cg8 + 4);
                u64t a0 = dup2(a2.x), a1 = dup2(a2.y);
                u64t b0 = __double_as_longlong(B0.x);
                u64t b1 = __double_as_longlong(B0.y);
                u64t b2 = __double_as_longlong(B1.x);
                u64t b3 = __double_as_longlong(B1.y);
                acc2[0][0] = fma2(a0, b0, acc2[0][0]);
                acc2[0][1] = fma2(a0, b1, acc2[0][1]);
                acc2[0][2] = fma2(a0, b2, acc2[0][2]);
                acc2[0][3] = fma2(a0, b3, acc2[0][3]);
                acc2[1][0] = fma2(a1, b0, acc2[1][0]);
                acc2[1][1] = fma2(a1, b1, acc2[1][1]);
                acc2[1][2] = fma2(a1, b2, acc2[1][2]);
                acc2[1][3] = fma2(a1, b3, acc2[1][3]);
            }

            // epilogue: adapted = x + u + bu; out += adapted * Wc^T
            #pragma unroll
            for (int j2 = 0; j2 < 4; j2++) {
                float2 u0 = upk(acc2[0][j2]);   // row 2rg,  cols (2j2, 2j2+1)
                float2 u1 = upk(acc2[1][j2]);   // row 2rg+1
                #pragma unroll
                for (int e = 0; e < 2; e++) {
                    int col = c0 + cg8 + 2 * j2 + e;
                    float buc = buv[col];
                    float wc0 = Wc[col];
                    float wc1 = Wc[HH + col];
                    float2 xv = *(const float2*)(sXt + col * XPAD + 2 * rg);
                    float ue0 = e ? u0.y : u0.x;
                    float ue1 = e ? u1.y : u1.x;
                    float ad0 = xv.x + ue0 + buc;
                    float ad1 = xv.y + ue1 + buc;
                    outacc[0][0] = fmaf(ad0, wc0, outacc[0][0]);
                    outacc[0][1] = fmaf(ad0, wc1, outacc[0][1]);
                    outacc[1][0] = fmaf(ad1, wc0, outacc[1][0]);
                    outacc[1][1] = fmaf(ad1, wc1, outacc[1][1]);
                }
            }
            __syncthreads();
        }

        // ---- reduce over 16 colgroups: xor-16 in warp, then cross-warp ----
        #pragma unroll
        for (int i = 0; i < 2; i++)
            #pragma unroll
            for (int l = 0; l < 2; l++)
                outacc[i][l] += __shfl_xor_sync(0xFFFFFFFFu, outacc[i][l], 16);

        float* sRed = sW;   // free after last sync
        if (ch == 0) {
            #pragma unroll
            for (int i = 0; i < 2; i++)
                #pragma unroll
                for (int l = 0; l < 2; l++)
                    sRed[((warp * 16 + rg) * 2 + i) * 2 + l] = outacc[i][l];
        }
        __syncthreads();
        if (tid < MTILE * LL) {
            int row = tid >> 1;
            int l   = tid & 1;
            float s = bc[l];
            #pragma unroll
            for (int w = 0; w < 8; w++)
                s += sRed[((w * 16 + (row >> 1)) * 2 + (row & 1)) * 2 + l];
            int b = sB[row];
            if (b >= 0) out[b * LL + l] = s;
        }
        __syncthreads();
    }
}

extern "C" void kernel_launch(void* const* d_in, const int* in_sizes, int n_in,
                              void* d_out, int out_size) {
    const float* lh   = (const float*)d_in[0];
    const int*   vids = (const int*)d_in[2];
    const float* Wd   = (const float*)d_in[3];
    const float* bd   = (const float*)d_in[4];
    const float* Wu   = (const float*)d_in[5];
    const float* bu   = (const float*)d_in[6];
    const float* Wc   = (const float*)d_in[7];
    const float* bc   = (const float*)d_in[8];
    float* out = (float*)d_out;

    size_t smem_bytes = SMEM_FLOATS * sizeof(float);
    cudaFuncSetAttribute(va_main, cudaFuncAttributeMaxDynamicSharedMemorySize,
                         (int)smem_bytes);

    va_zero_counts<<<1, 32>>>();
    va_bin<<<BB / 256, 256>>>(vids);
    va_build_tiles<<<1, 32>>>();
    va_main<<<148, NTHREADS, smem_bytes>>>(lh, Wd, bd, Wu, bu, Wc, bc, out);
}